// round 6
// baseline (speedup 1.0000x reference)
#include <cuda_runtime.h>
#include <cuda_bf16.h>
#include <cstdint>
#include <math.h>

// ======================= problem dims =======================
#define UU      356
#define GATES   1424
#define BSZ     8192
#define TS      7
#define FENC    69
#define FDEC    45
#define H1      1024
#define OUTN    168

#define HPAD    384
#define XPAD    128
#define MPAD    64
#define DPAD    2496
#define GNPAD   1536
#define ONPAD   256
#define BT      (BSZ*TS)

typedef __nv_bfloat16 bf16;

// ======================= scratch (device globals) =======================
__device__ bf16 g_xhi[(size_t)BT*XPAD],  g_xlo[(size_t)BT*XPAD];
__device__ bf16 g_mhi[(size_t)BT*MPAD],  g_mlo[(size_t)BT*MPAD];
__device__ float g_xw[(size_t)BT*GATES];          // permuted gate order 4j+g
__device__ float g_c [(size_t)BSZ*UU];
// ping-pong h buffers (race fix: step t reads [t&1], writes [(t+1)&1])
__device__ bf16 g_hhi0[(size_t)BSZ*HPAD], g_hlo0[(size_t)BSZ*HPAD];
__device__ bf16 g_hhi1[(size_t)BSZ*HPAD], g_hlo1[(size_t)BSZ*HPAD];
__device__ bf16 g_dhi[(size_t)BSZ*DPAD], g_dlo[(size_t)BSZ*DPAD];
__device__ bf16 g_t1hi[(size_t)BSZ*H1], g_t1lo[(size_t)BSZ*H1];
__device__ bf16 g_t2hi[(size_t)BSZ*H1], g_t2lo[(size_t)BSZ*H1];
// transposed + split weights, padded [Npad, Kpad]; LSTM ones gate-permuted
__device__ bf16 w_encW_hi[(size_t)GNPAD*XPAD], w_encW_lo[(size_t)GNPAD*XPAD];
__device__ bf16 w_decW_hi[(size_t)GNPAD*MPAD], w_decW_lo[(size_t)GNPAD*MPAD];
__device__ bf16 w_encU_hi[(size_t)GNPAD*HPAD], w_encU_lo[(size_t)GNPAD*HPAD];
__device__ bf16 w_decU_hi[(size_t)GNPAD*HPAD], w_decU_lo[(size_t)GNPAD*HPAD];
__device__ bf16 w_map_hi[(size_t)H1*DPAD],     w_map_lo[(size_t)H1*DPAD];
__device__ bf16 w_1_hi[(size_t)H1*H1], w_1_lo[(size_t)H1*H1];
__device__ bf16 w_2_hi[(size_t)H1*H1], w_2_lo[(size_t)H1*H1];
__device__ bf16 w_3_hi[(size_t)H1*H1], w_3_lo[(size_t)H1*H1];
__device__ bf16 w_out_hi[(size_t)ONPAD*H1],    w_out_lo[(size_t)ONPAD*H1];

// ======================= PTX helpers (sm_80-era) =======================
__device__ __forceinline__ uint32_t smem_u32(const void* p) {
    uint32_t a;
    asm("{ .reg .u64 t; cvta.to.shared.u64 t, %1; cvt.u32.u64 %0, t; }" : "=r"(a) : "l"(p));
    return a;
}
#define CP_ASYNC16(dst, src) \
    asm volatile("cp.async.cg.shared.global [%0], [%1], 16;" :: "r"(dst), "l"(src))
#define CP_COMMIT()  asm volatile("cp.async.commit_group;" ::: "memory")
#define CP_WAIT1()   asm volatile("cp.async.wait_group 1;" ::: "memory")
#define LDSM4(r0,r1,r2,r3,addr) \
    asm volatile("ldmatrix.sync.aligned.m8n8.x4.shared.b16 {%0,%1,%2,%3}, [%4];" \
        : "=r"(r0),"=r"(r1),"=r"(r2),"=r"(r3) : "r"(addr))

__device__ __forceinline__ void mma16816(float* d, const uint32_t* a, const uint32_t* b) {
    asm volatile("mma.sync.aligned.m16n8k16.row.col.f32.bf16.bf16.f32 "
        "{%0,%1,%2,%3}, {%4,%5,%6,%7}, {%8,%9}, {%0,%1,%2,%3};"
        : "+f"(d[0]), "+f"(d[1]), "+f"(d[2]), "+f"(d[3])
        : "r"(a[0]), "r"(a[1]), "r"(a[2]), "r"(a[3]), "r"(b[0]), "r"(b[1]));
}

__device__ __forceinline__ void split2(float v, bf16& hi, bf16& lo) {
    hi = __float2bfloat16(v);
    lo = __float2bfloat16(v - __bfloat162float(hi));
}

// ======================= HMMA GEMM =======================
// C[M,N] = epi( A @ B^T (+Ci) (+bias) )
// CTA 256x128, BK=32, 8 warps (4 M x 2 N), warp tile 64x64, 3-stage cp.async.
#define ROWB    80
#define A_TILEB (256*ROWB)
#define B_TILEB (128*ROWB)
#define STAGE   (2*A_TILEB + 2*B_TILEB)    // 61440
#define NSTAGE  3
#define SMEM_BYTES (NSTAGE*STAGE)          // 184320
#define CSP 33                             // smem pitch (words) for gate staging

template<int ACT, bool BIAS, bool CINIT, bool WF32, bool WSPLIT, bool GATE>
__global__ __launch_bounds__(256)
void mma_gemm(int M, int N, int Kpad,
              const bf16* __restrict__ Ahi, const bf16* __restrict__ Alo,
              const bf16* __restrict__ Bhi, const bf16* __restrict__ Blo,
              const float* __restrict__ bias, int permb,
              const float* __restrict__ Ci, int ldci,
              float* __restrict__ Cf, int ldc,
              bf16* __restrict__ Chi, bf16* __restrict__ Clo, int ldcs,
              float* __restrict__ cst,
              bf16* __restrict__ hhi, bf16* __restrict__ hlo,
              bf16* __restrict__ dhi, bf16* __restrict__ dlo, int tstep)
{
    extern __shared__ char smem[];
    const uint32_t sbase = smem_u32(smem);
    const int tid  = threadIdx.x;
    const int lane = tid & 31;
    const int wid  = tid >> 5;
    const int warp_m = wid & 3;
    const int warp_n = wid >> 2;
    const int bm = blockIdx.y * 256;
    const int bn = blockIdx.x * 128;

    const int ld = Kpad * 2;
    const char* gAhi = (const char*)Ahi + (size_t)bm * ld;
    const char* gAlo = (const char*)Alo + (size_t)bm * ld;
    const char* gBhi = (const char*)Bhi + (size_t)bn * ld;
    const char* gBlo = (const char*)Blo + (size_t)bn * ld;

    const int rr  = tid >> 2;
    const int seg = (tid & 3) * 16;

    float acc[4][8][4];
    #pragma unroll
    for (int i = 0; i < 4; i++)
        #pragma unroll
        for (int j = 0; j < 8; j++)
            #pragma unroll
            for (int q = 0; q < 4; q++) acc[i][j][q] = 0.f;

    const int NC = Kpad >> 5;

    auto stage_load = [&](int c) {
        uint32_t s = sbase + (c % NSTAGE) * STAGE;
        int ko = c << 6;
        #pragma unroll
        for (int i = 0; i < 4; i++) {
            int r = rr + i * 64;
            CP_ASYNC16(s + 0*A_TILEB + r*ROWB + seg, gAhi + (size_t)r*ld + ko + seg);
            CP_ASYNC16(s + 1*A_TILEB + r*ROWB + seg, gAlo + (size_t)r*ld + ko + seg);
        }
        #pragma unroll
        for (int i = 0; i < 2; i++) {
            int r = rr + i * 64;
            CP_ASYNC16(s + 2*A_TILEB + 0*B_TILEB + r*ROWB + seg, gBhi + (size_t)r*ld + ko + seg);
            CP_ASYNC16(s + 2*A_TILEB + 1*B_TILEB + r*ROWB + seg, gBlo + (size_t)r*ld + ko + seg);
        }
    };

    stage_load(0); CP_COMMIT();
    if (NC > 1) { stage_load(1); }
    CP_COMMIT();

    const uint32_t aoff = (uint32_t)((warp_m*64 + (lane & 15)) * ROWB + (lane >> 4) * 16);
    const uint32_t boff = (uint32_t)((warp_n*64 + (lane >> 4)*8 + (lane & 7)) * ROWB
                                     + ((lane >> 3) & 1) * 16);

    for (int c = 0; c < NC; c++) {
        CP_WAIT1();
        __syncthreads();
        if (c + 2 < NC) stage_load(c + 2);
        CP_COMMIT();

        const uint32_t sb = sbase + (c % NSTAGE) * STAGE;
        const uint32_t sa0 = sb;
        const uint32_t sa1 = sb + A_TILEB;
        const uint32_t sb0 = sb + 2*A_TILEB;
        const uint32_t sb1 = sb0 + B_TILEB;

        #pragma unroll
        for (int kk = 0; kk < 2; kk++) {
            const uint32_t kb = kk * 32;
            uint32_t ahi[4][4], alo[4][4], bhi[4][4], blo[4][4];
            #pragma unroll
            for (int mi = 0; mi < 4; mi++) {
                uint32_t a = aoff + mi * (16 * ROWB) + kb;
                LDSM4(ahi[mi][0], ahi[mi][1], ahi[mi][2], ahi[mi][3], sa0 + a);
                LDSM4(alo[mi][0], alo[mi][1], alo[mi][2], alo[mi][3], sa1 + a);
            }
            #pragma unroll
            for (int g = 0; g < 4; g++) {
                uint32_t b = boff + g * (16 * ROWB) + kb;
                LDSM4(bhi[g][0], bhi[g][1], bhi[g][2], bhi[g][3], sb0 + b);
                LDSM4(blo[g][0], blo[g][1], blo[g][2], blo[g][3], sb1 + b);
            }
            #pragma unroll
            for (int mi = 0; mi < 4; mi++)
                #pragma unroll
                for (int nj = 0; nj < 8; nj++) {
                    const uint32_t* bh = &bhi[nj >> 1][(nj & 1) * 2];
                    const uint32_t* bl = &blo[nj >> 1][(nj & 1) * 2];
                    mma16816(acc[mi][nj], ahi[mi], bh);
                    mma16816(acc[mi][nj], ahi[mi], bl);
                    mma16816(acc[mi][nj], alo[mi], bh);
                }
        }
        __syncthreads();
    }

    const int tr = lane >> 2;
    const int tc = (lane & 3) * 2;
    const int row0 = bm + warp_m * 64;
    const int col0 = bn + warp_n * 64;

    if (GATE) {
        // ---- fused LSTM cell epilogue ----
        // columns are permuted gates: gc = 4*j + g; 128-col tile = 32 units
        float* c_s = (float*)smem;              // [256][CSP]
        float* h_s = c_s + 256 * CSP;
        const int j_base = bn >> 2;

        #pragma unroll 4
        for (int i = 0; i < 32; i++) {
            int row = wid * 32 + i;
            int j = j_base + lane;
            c_s[row * CSP + lane] = (j < UU) ? cst[(size_t)(bm + row) * UU + j] : 0.f;
        }
        __syncthreads();

        const int q = lane & 3;                 // q even: holds (i,f); q odd: holds (g,o)
        #pragma unroll
        for (int mi = 0; mi < 4; mi++)
            #pragma unroll
            for (int nj = 0; nj < 8; nj++) {
                int gc = col0 + nj * 8 + tc;
                int unit_local = warp_n * 16 + nj * 2 + (q >> 1);
                #pragma unroll
                for (int hh = 0; hh < 2; hh++) {
                    int gr = row0 + mi * 16 + hh * 8 + tr;
                    float v0 = acc[mi][nj][hh * 2 + 0];
                    float v1 = acc[mi][nj][hh * 2 + 1];
                    if (CINIT && gc < N) {
                        const float* ci = Ci + (size_t)gr * ldci + gc;
                        v0 += ci[0]; v1 += ci[1];
                    }
                    float p0 = __shfl_xor_sync(0xffffffffu, v0, 1);
                    float p1 = __shfl_xor_sync(0xffffffffu, v1, 1);
                    if ((q & 1) == 0) {
                        // this lane: (i,f) = (v0,v1); partner: (g,o) = (p0,p1)
                        float ig = 1.f / (1.f + expf(-v0));
                        float fg = 1.f / (1.f + expf(-v1));
                        float gg = tanhf(p0);
                        float og = 1.f / (1.f + expf(-p1));
                        int rloc = warp_m * 64 + mi * 16 + hh * 8 + tr;
                        float cn = fg * c_s[rloc * CSP + unit_local] + ig * gg;
                        c_s[rloc * CSP + unit_local] = cn;
                        h_s[rloc * CSP + unit_local] = og * tanhf(cn);
                    }
                }
            }
        __syncthreads();

        #pragma unroll 4
        for (int i = 0; i < 32; i++) {
            int row = wid * 32 + i;
            int j = j_base + lane;
            if (j < UU) {
                int gr = bm + row;
                cst[(size_t)gr * UU + j] = c_s[row * CSP + lane];
                float hv = h_s[row * CSP + lane];
                bf16 hi, lo; split2(hv, hi, lo);
                hhi[(size_t)gr * HPAD + j] = hi;
                hlo[(size_t)gr * HPAD + j] = lo;
                if (dhi) {
                    dhi[(size_t)gr * DPAD + tstep * UU + j] = hi;
                    dlo[(size_t)gr * DPAD + tstep * UU + j] = lo;
                }
            }
        }
        return;
    }

    // ---- standard epilogue ----
    #pragma unroll
    for (int mi = 0; mi < 4; mi++)
        #pragma unroll
        for (int nj = 0; nj < 8; nj++) {
            int gc = col0 + nj * 8 + tc;
            if (gc >= N) continue;
            float b0 = 0.f, b1 = 0.f;
            if (BIAS) {
                if (permb) {
                    b0 = bias[(gc & 3) * UU + (gc >> 2)];
                    b1 = bias[((gc + 1) & 3) * UU + ((gc + 1) >> 2)];
                } else {
                    b0 = bias[gc]; b1 = bias[gc + 1];
                }
            }
            #pragma unroll
            for (int hh = 0; hh < 2; hh++) {
                int gr = row0 + mi * 16 + hh * 8 + tr;
                float v0 = acc[mi][nj][hh * 2 + 0];
                float v1 = acc[mi][nj][hh * 2 + 1];
                if (CINIT) {
                    const float* ci = Ci + (size_t)gr * ldci + gc;
                    v0 += ci[0]; v1 += ci[1];
                }
                if (BIAS) { v0 += b0; v1 += b1; }
                if (ACT == 1) { v0 = fmaxf(v0, 0.f); v1 = fmaxf(v1, 0.f); }
                else if (ACT == 2) { v0 = tanhf(v0); v1 = tanhf(v1); }
                if (WF32) {
                    float2* p = (float2*)(Cf + (size_t)gr * ldc + gc);
                    *p = make_float2(v0, v1);
                }
                if (WSPLIT) {
                    bf16 h0, l0, h1, l1;
                    split2(v0, h0, l0); split2(v1, h1, l1);
                    *(__nv_bfloat162*)(Chi + (size_t)gr * ldcs + gc) = __nv_bfloat162(h0, h1);
                    *(__nv_bfloat162*)(Clo + (size_t)gr * ldcs + gc) = __nv_bfloat162(l0, l1);
                }
            }
        }
}

// ======================= prep kernels =======================
__global__ void prep_weight(const float* __restrict__ W, int K, int N, int Kpad, int total,
                            int perm, bf16* __restrict__ Whi, bf16* __restrict__ Wlo)
{
    int idx = blockIdx.x * blockDim.x + threadIdx.x;
    if (idx >= total) return;
    int n = idx / Kpad, k = idx - n * Kpad;
    int nsrc = perm ? ((n & 3) * UU + (n >> 2)) : n;
    int valid = perm ? ((n >> 2) < UU) : (n < N);
    float v = (k < K && valid) ? W[(size_t)k * N + nsrc] : 0.f;
    bf16 hi, lo; split2(v, hi, lo);
    Whi[idx] = hi; Wlo[idx] = lo;
}

__global__ void prep_act(const float* __restrict__ X, int total, int K, int Kpad,
                         bf16* __restrict__ Ahi, bf16* __restrict__ Alo)
{
    int idx = blockIdx.x * blockDim.x + threadIdx.x;
    if (idx >= total) return;
    int r = idx / Kpad, k = idx - r * Kpad;
    float v = (k < K) ? X[(size_t)r * K + k] : 0.f;
    bf16 hi, lo; split2(v, hi, lo);
    Ahi[idx] = hi; Alo[idx] = lo;
}

// ======================= host side =======================
template<int ACT, bool BIAS, bool CINIT, bool WF32, bool WSPLIT, bool GATE>
static inline void launch_mma(int M, int N, int Kpad,
                              const bf16* Ahi, const bf16* Alo,
                              const bf16* Bhi, const bf16* Blo,
                              const float* bias, int permb,
                              const float* Ci, int ldci,
                              float* Cf, int ldc, bf16* Chi, bf16* Clo, int ldcs,
                              float* cst = nullptr, bf16* hhi = nullptr, bf16* hlo = nullptr,
                              bf16* dhi = nullptr, bf16* dlo = nullptr, int tstep = 0)
{
    dim3 grid((N + 127) / 128, M / 256);
    mma_gemm<ACT, BIAS, CINIT, WF32, WSPLIT, GATE><<<grid, 256, SMEM_BYTES>>>(
        M, N, Kpad, Ahi, Alo, Bhi, Blo, bias, permb, Ci, ldci, Cf, ldc, Chi, Clo, ldcs,
        cst, hhi, hlo, dhi, dlo, tstep);
}

static inline void set_attrs() {
    cudaFuncSetAttribute(mma_gemm<0, true,  false, true,  false, false>, cudaFuncAttributeMaxDynamicSharedMemorySize, SMEM_BYTES);
    cudaFuncSetAttribute(mma_gemm<0, false, true,  false, false, true >, cudaFuncAttributeMaxDynamicSharedMemorySize, SMEM_BYTES);
    cudaFuncSetAttribute(mma_gemm<1, true,  false, false, true,  false>, cudaFuncAttributeMaxDynamicSharedMemorySize, SMEM_BYTES);
    cudaFuncSetAttribute(mma_gemm<2, true,  false, false, true,  false>, cudaFuncAttributeMaxDynamicSharedMemorySize, SMEM_BYTES);
}

extern "C" void kernel_launch(void* const* d_in, const int* /*in_sizes*/, int /*n_in*/,
                              void* d_out, int /*out_size*/)
{
    const float* x     = (const float*)d_in[0];
    const float* m     = (const float*)d_in[1];
    const float* enc_W = (const float*)d_in[2];
    const float* enc_U = (const float*)d_in[3];
    const float* enc_b = (const float*)d_in[4];
    const float* dec_W = (const float*)d_in[5];
    const float* dec_U = (const float*)d_in[6];
    const float* dec_b = (const float*)d_in[7];
    const float* W_map = (const float*)d_in[8];
    const float* b_map = (const float*)d_in[9];
    const float* W1    = (const float*)d_in[10];
    const float* b1    = (const float*)d_in[11];
    const float* W2    = (const float*)d_in[12];
    const float* b2    = (const float*)d_in[13];
    const float* W3    = (const float*)d_in[14];
    const float* b3    = (const float*)d_in[15];
    const float* W_out = (const float*)d_in[16];
    const float* b_out = (const float*)d_in[17];
    float* out = (float*)d_out;

    set_attrs();

    bf16 *xhi,*xlo,*mhi,*mlo,*dhi,*dlo,*t1hi,*t1lo,*t2hi,*t2lo;
    bf16 *hh[2], *hl[2];
    bf16 *eWh,*eWl,*dWh,*dWl,*eUh,*eUl,*dUh,*dUl,*wmh,*wml,*w1h,*w1l,*w2h,*w2l,*w3h,*w3l,*woh,*wol;
    float *xw,*c;
    cudaGetSymbolAddress((void**)&xhi, g_xhi);  cudaGetSymbolAddress((void**)&xlo, g_xlo);
    cudaGetSymbolAddress((void**)&mhi, g_mhi);  cudaGetSymbolAddress((void**)&mlo, g_mlo);
    cudaGetSymbolAddress((void**)&hh[0], g_hhi0); cudaGetSymbolAddress((void**)&hl[0], g_hlo0);
    cudaGetSymbolAddress((void**)&hh[1], g_hhi1); cudaGetSymbolAddress((void**)&hl[1], g_hlo1);
    cudaGetSymbolAddress((void**)&dhi, g_dhi);  cudaGetSymbolAddress((void**)&dlo, g_dlo);
    cudaGetSymbolAddress((void**)&t1hi, g_t1hi); cudaGetSymbolAddress((void**)&t1lo, g_t1lo);
    cudaGetSymbolAddress((void**)&t2hi, g_t2hi); cudaGetSymbolAddress((void**)&t2lo, g_t2lo);
    cudaGetSymbolAddress((void**)&eWh, w_encW_hi); cudaGetSymbolAddress((void**)&eWl, w_encW_lo);
    cudaGetSymbolAddress((void**)&dWh, w_decW_hi); cudaGetSymbolAddress((void**)&dWl, w_decW_lo);
    cudaGetSymbolAddress((void**)&eUh, w_encU_hi); cudaGetSymbolAddress((void**)&eUl, w_encU_lo);
    cudaGetSymbolAddress((void**)&dUh, w_decU_hi); cudaGetSymbolAddress((void**)&dUl, w_decU_lo);
    cudaGetSymbolAddress((void**)&wmh, w_map_hi);  cudaGetSymbolAddress((void**)&wml, w_map_lo);
    cudaGetSymbolAddress((void**)&w1h, w_1_hi);    cudaGetSymbolAddress((void**)&w1l, w_1_lo);
    cudaGetSymbolAddress((void**)&w2h, w_2_hi);    cudaGetSymbolAddress((void**)&w2l, w_2_lo);
    cudaGetSymbolAddress((void**)&w3h, w_3_hi);    cudaGetSymbolAddress((void**)&w3l, w_3_lo);
    cudaGetSymbolAddress((void**)&woh, w_out_hi);  cudaGetSymbolAddress((void**)&wol, w_out_lo);
    cudaGetSymbolAddress((void**)&xw, g_xw);
    cudaGetSymbolAddress((void**)&c,  g_c);

    cudaMemsetAsync(c,     0, (size_t)BSZ * UU * sizeof(float));
    cudaMemsetAsync(hh[0], 0, (size_t)BSZ * HPAD * sizeof(bf16));
    cudaMemsetAsync(hl[0], 0, (size_t)BSZ * HPAD * sizeof(bf16));

    auto pw = [](const float* W, int K, int N, int Kpad, int Npad, int perm, bf16* hi, bf16* lo) {
        int total = Npad * Kpad;
        prep_weight<<<(total + 255) / 256, 256>>>(W, K, N, Kpad, total, perm, hi, lo);
    };
    pw(enc_W, FENC, GATES, XPAD, GNPAD, 1, eWh, eWl);
    pw(dec_W, FDEC, GATES, MPAD, GNPAD, 1, dWh, dWl);
    pw(enc_U, UU,   GATES, HPAD, GNPAD, 1, eUh, eUl);
    pw(dec_U, UU,   GATES, HPAD, GNPAD, 1, dUh, dUl);
    pw(W_map, TS*UU, H1, DPAD, H1, 0, wmh, wml);
    pw(W1, H1, H1, H1, H1, 0, w1h, w1l);
    pw(W2, H1, H1, H1, H1, 0, w2h, w2l);
    pw(W3, H1, H1, H1, H1, 0, w3h, w3l);
    pw(W_out, H1, OUTN, H1, ONPAD, 0, woh, wol);

    {
        int tot = BT * XPAD;
        prep_act<<<(tot + 255) / 256, 256>>>(x, tot, FENC, XPAD, xhi, xlo);
        tot = BT * MPAD;
        prep_act<<<(tot + 255) / 256, 256>>>(m, tot, FDEC, MPAD, mhi, mlo);
    }

    // encoder input projection (permuted bias): xw = x @ enc_W' + enc_b'
    launch_mma<0, true, false, true, false, false>(BT, GATES, XPAD, xhi, xlo, eWh, eWl,
                                                   enc_b, 1, nullptr, 0, xw, GATES,
                                                   nullptr, nullptr, 0);
    int pb = 0;  // ping-pong parity: h state currently in hh[pb]
    for (int t = 0; t < TS; t++) {
        launch_mma<0, false, true, false, false, true>(BSZ, GATES, HPAD,
                                                       hh[pb], hl[pb], eUh, eUl,
                                                       nullptr, 0, xw + (size_t)t * GATES, TS * GATES,
                                                       nullptr, 0, nullptr, nullptr, 0,
                                                       c, hh[pb ^ 1], hl[pb ^ 1], nullptr, nullptr, 0);
        pb ^= 1;
    }

    // decoder input projection (reuse xw)
    launch_mma<0, true, false, true, false, false>(BT, GATES, MPAD, mhi, mlo, dWh, dWl,
                                                   dec_b, 1, nullptr, 0, xw, GATES,
                                                   nullptr, nullptr, 0);
    for (int t = 0; t < TS; t++) {
        launch_mma<0, false, true, false, false, true>(BSZ, GATES, HPAD,
                                                       hh[pb], hl[pb], dUh, dUl,
                                                       nullptr, 0, xw + (size_t)t * GATES, TS * GATES,
                                                       nullptr, 0, nullptr, nullptr, 0,
                                                       c, hh[pb ^ 1], hl[pb ^ 1], dhi, dlo, t);
        pb ^= 1;
    }

    // MLP head
    launch_mma<1, true, false, false, true, false>(BSZ, H1, DPAD, dhi, dlo, wmh, wml,
                                                   b_map, 0, nullptr, 0, nullptr, 0, t1hi, t1lo, H1);
    launch_mma<2, true, false, false, true, false>(BSZ, H1, H1, t1hi, t1lo, w1h, w1l,
                                                   b1, 0, nullptr, 0, nullptr, 0, t2hi, t2lo, H1);
    launch_mma<2, true, false, false, true, false>(BSZ, H1, H1, t2hi, t2lo, w2h, w2l,
                                                   b2, 0, nullptr, 0, nullptr, 0, t1hi, t1lo, H1);
    launch_mma<2, true, false, false, true, false>(BSZ, H1, H1, t1hi, t1lo, w3h, w3l,
                                                   b3, 0, nullptr, 0, nullptr, 0, t2hi, t2lo, H1);
    launch_mma<0, true, false, true, false, false>(BSZ, OUTN, H1, t2hi, t2lo, woh, wol,
                                                   b_out, 0, nullptr, 0, out, OUTN, nullptr, nullptr, 0);
}

// round 7
// speedup vs baseline: 1.4611x; 1.4611x over previous
#include <cuda_runtime.h>
#include <cuda_bf16.h>
#include <cstdint>
#include <math.h>

// ======================= problem dims =======================
#define UU      356
#define GATES   1424
#define BSZ     8192
#define TS      7
#define FENC    69
#define FDEC    45
#define H1      1024
#define OUTN    168

#define HPAD    384
#define XPAD    128
#define MPAD    64
#define DPAD    2496
#define GNPAD   1536
#define ONPAD   256
#define BT      (BSZ*TS)

typedef __nv_bfloat16 bf16;

// ======================= scratch (device globals) =======================
__device__ bf16 g_xhi[(size_t)BT*XPAD],  g_xlo[(size_t)BT*XPAD];
__device__ bf16 g_mhi[(size_t)BT*MPAD],  g_mlo[(size_t)BT*MPAD];
__device__ float g_xw[(size_t)BT*GATES];
__device__ float g_z [(size_t)BSZ*GATES];
__device__ float g_c [(size_t)BSZ*UU];
__device__ bf16 g_hhi[(size_t)BSZ*HPAD], g_hlo[(size_t)BSZ*HPAD];
__device__ bf16 g_dhi[(size_t)BSZ*DPAD], g_dlo[(size_t)BSZ*DPAD];
__device__ bf16 g_t1hi[(size_t)BSZ*H1], g_t1lo[(size_t)BSZ*H1];
__device__ bf16 g_t2hi[(size_t)BSZ*H1], g_t2lo[(size_t)BSZ*H1];
// transposed + split weights, padded [Npad, Kpad]
__device__ bf16 w_encW_hi[(size_t)GNPAD*XPAD], w_encW_lo[(size_t)GNPAD*XPAD];
__device__ bf16 w_decW_hi[(size_t)GNPAD*MPAD], w_decW_lo[(size_t)GNPAD*MPAD];
__device__ bf16 w_encU_hi[(size_t)GNPAD*HPAD], w_encU_lo[(size_t)GNPAD*HPAD];
__device__ bf16 w_decU_hi[(size_t)GNPAD*HPAD], w_decU_lo[(size_t)GNPAD*HPAD];
__device__ bf16 w_map_hi[(size_t)H1*DPAD],     w_map_lo[(size_t)H1*DPAD];
__device__ bf16 w_1_hi[(size_t)H1*H1], w_1_lo[(size_t)H1*H1];
__device__ bf16 w_2_hi[(size_t)H1*H1], w_2_lo[(size_t)H1*H1];
__device__ bf16 w_3_hi[(size_t)H1*H1], w_3_lo[(size_t)H1*H1];
__device__ bf16 w_out_hi[(size_t)ONPAD*H1],    w_out_lo[(size_t)ONPAD*H1];

// ======================= PTX helpers (sm_80-era) =======================
__device__ __forceinline__ uint32_t smem_u32(const void* p) {
    uint32_t a;
    asm("{ .reg .u64 t; cvta.to.shared.u64 t, %1; cvt.u32.u64 %0, t; }" : "=r"(a) : "l"(p));
    return a;
}
#define CP_ASYNC16(dst, src) \
    asm volatile("cp.async.cg.shared.global [%0], [%1], 16;" :: "r"(dst), "l"(src))
#define CP_COMMIT()  asm volatile("cp.async.commit_group;" ::: "memory")
#define CP_WAIT1()   asm volatile("cp.async.wait_group 1;" ::: "memory")
#define LDSM4(r0,r1,r2,r3,addr) \
    asm volatile("ldmatrix.sync.aligned.m8n8.x4.shared.b16 {%0,%1,%2,%3}, [%4];" \
        : "=r"(r0),"=r"(r1),"=r"(r2),"=r"(r3) : "r"(addr))

__device__ __forceinline__ void mma16816(float* d, const uint32_t* a, const uint32_t* b) {
    asm volatile("mma.sync.aligned.m16n8k16.row.col.f32.bf16.bf16.f32 "
        "{%0,%1,%2,%3}, {%4,%5,%6,%7}, {%8,%9}, {%0,%1,%2,%3};"
        : "+f"(d[0]), "+f"(d[1]), "+f"(d[2]), "+f"(d[3])
        : "r"(a[0]), "r"(a[1]), "r"(a[2]), "r"(a[3]), "r"(b[0]), "r"(b[1]));
}

__device__ __forceinline__ void split2(float v, bf16& hi, bf16& lo) {
    hi = __float2bfloat16(v);
    lo = __float2bfloat16(v - __bfloat162float(hi));
}

// fast transcendentals (MUFU-based, rel err ~1e-6 — far below bf16-split error)
__device__ __forceinline__ float fsig(float x) {
    return __fdividef(1.f, 1.f + __expf(-x));
}
__device__ __forceinline__ float ftanh(float x) {
    return __fmaf_rn(2.f, fsig(2.f * x), -1.f);
}

// ======================= HMMA GEMM =======================
// C[M,N] = act( A @ B^T (+Ci) (+bias) )
// CTA 256x128, BK=32, 8 warps (4 M x 2 N), warp tile 64x64, 3-stage cp.async.
#define ROWB    80
#define A_TILEB (256*ROWB)
#define B_TILEB (128*ROWB)
#define STAGE   (2*A_TILEB + 2*B_TILEB)    // 61440
#define NSTAGE  3
#define SMEM_BYTES (NSTAGE*STAGE)          // 184320

template<int ACT, bool BIAS, bool CINIT, bool WF32, bool WSPLIT>
__global__ __launch_bounds__(256)
void mma_gemm(int M, int N, int Kpad,
              const bf16* __restrict__ Ahi, const bf16* __restrict__ Alo,
              const bf16* __restrict__ Bhi, const bf16* __restrict__ Blo,
              const float* __restrict__ bias,
              const float* __restrict__ Ci, int ldci,
              float* __restrict__ Cf, int ldc,
              bf16* __restrict__ Chi, bf16* __restrict__ Clo, int ldcs)
{
    extern __shared__ char smem[];
    const uint32_t sbase = smem_u32(smem);
    const int tid  = threadIdx.x;
    const int lane = tid & 31;
    const int wid  = tid >> 5;
    const int warp_m = wid & 3;
    const int warp_n = wid >> 2;
    const int bm = blockIdx.y * 256;
    const int bn = blockIdx.x * 128;

    const int ld = Kpad * 2;
    const char* gAhi = (const char*)Ahi + (size_t)bm * ld;
    const char* gAlo = (const char*)Alo + (size_t)bm * ld;
    const char* gBhi = (const char*)Bhi + (size_t)bn * ld;
    const char* gBlo = (const char*)Blo + (size_t)bn * ld;

    const int rr  = tid >> 2;
    const int seg = (tid & 3) * 16;

    float acc[4][8][4];
    #pragma unroll
    for (int i = 0; i < 4; i++)
        #pragma unroll
        for (int j = 0; j < 8; j++)
            #pragma unroll
            for (int q = 0; q < 4; q++) acc[i][j][q] = 0.f;

    const int NC = Kpad >> 5;

    auto stage_load = [&](int c) {
        uint32_t s = sbase + (c % NSTAGE) * STAGE;
        int ko = c << 6;
        #pragma unroll
        for (int i = 0; i < 4; i++) {
            int r = rr + i * 64;
            CP_ASYNC16(s + 0*A_TILEB + r*ROWB + seg, gAhi + (size_t)r*ld + ko + seg);
            CP_ASYNC16(s + 1*A_TILEB + r*ROWB + seg, gAlo + (size_t)r*ld + ko + seg);
        }
        #pragma unroll
        for (int i = 0; i < 2; i++) {
            int r = rr + i * 64;
            CP_ASYNC16(s + 2*A_TILEB + 0*B_TILEB + r*ROWB + seg, gBhi + (size_t)r*ld + ko + seg);
            CP_ASYNC16(s + 2*A_TILEB + 1*B_TILEB + r*ROWB + seg, gBlo + (size_t)r*ld + ko + seg);
        }
    };

    stage_load(0); CP_COMMIT();
    if (NC > 1) { stage_load(1); }
    CP_COMMIT();

    const uint32_t aoff = (uint32_t)((warp_m*64 + (lane & 15)) * ROWB + (lane >> 4) * 16);
    const uint32_t boff = (uint32_t)((warp_n*64 + (lane >> 4)*8 + (lane & 7)) * ROWB
                                     + ((lane >> 3) & 1) * 16);

    for (int c = 0; c < NC; c++) {
        CP_WAIT1();
        __syncthreads();
        if (c + 2 < NC) stage_load(c + 2);
        CP_COMMIT();

        const uint32_t sb = sbase + (c % NSTAGE) * STAGE;
        const uint32_t sa0 = sb;
        const uint32_t sa1 = sb + A_TILEB;
        const uint32_t sb0 = sb + 2*A_TILEB;
        const uint32_t sb1 = sb0 + B_TILEB;

        #pragma unroll
        for (int kk = 0; kk < 2; kk++) {
            const uint32_t kb = kk * 32;
            uint32_t ahi[4][4], alo[4][4], bhi[4][4], blo[4][4];
            #pragma unroll
            for (int mi = 0; mi < 4; mi++) {
                uint32_t a = aoff + mi * (16 * ROWB) + kb;
                LDSM4(ahi[mi][0], ahi[mi][1], ahi[mi][2], ahi[mi][3], sa0 + a);
                LDSM4(alo[mi][0], alo[mi][1], alo[mi][2], alo[mi][3], sa1 + a);
            }
            #pragma unroll
            for (int g = 0; g < 4; g++) {
                uint32_t b = boff + g * (16 * ROWB) + kb;
                LDSM4(bhi[g][0], bhi[g][1], bhi[g][2], bhi[g][3], sb0 + b);
                LDSM4(blo[g][0], blo[g][1], blo[g][2], blo[g][3], sb1 + b);
            }
            #pragma unroll
            for (int mi = 0; mi < 4; mi++)
                #pragma unroll
                for (int nj = 0; nj < 8; nj++) {
                    const uint32_t* bh = &bhi[nj >> 1][(nj & 1) * 2];
                    const uint32_t* bl = &blo[nj >> 1][(nj & 1) * 2];
                    mma16816(acc[mi][nj], ahi[mi], bh);
                    mma16816(acc[mi][nj], ahi[mi], bl);
                    mma16816(acc[mi][nj], alo[mi], bh);
                }
        }
        __syncthreads();
    }

    // ---- epilogue: registers -> global ----
    const int tr = lane >> 2;
    const int tc = (lane & 3) * 2;
    const int row0 = bm + warp_m * 64;
    const int col0 = bn + warp_n * 64;
    #pragma unroll
    for (int mi = 0; mi < 4; mi++)
        #pragma unroll
        for (int nj = 0; nj < 8; nj++) {
            int gc = col0 + nj * 8 + tc;
            if (gc >= N) continue;
            float b0 = 0.f, b1 = 0.f;
            if (BIAS) { b0 = bias[gc]; b1 = bias[gc + 1]; }
            #pragma unroll
            for (int hh = 0; hh < 2; hh++) {
                int gr = row0 + mi * 16 + hh * 8 + tr;
                float v0 = acc[mi][nj][hh * 2 + 0];
                float v1 = acc[mi][nj][hh * 2 + 1];
                if (CINIT) {
                    const float* ci = Ci + (size_t)gr * ldci + gc;
                    v0 += ci[0]; v1 += ci[1];
                }
                if (BIAS) { v0 += b0; v1 += b1; }
                if (ACT == 1) { v0 = fmaxf(v0, 0.f); v1 = fmaxf(v1, 0.f); }
                else if (ACT == 2) { v0 = ftanh(v0); v1 = ftanh(v1); }
                if (WF32) {
                    float2* p = (float2*)(Cf + (size_t)gr * ldc + gc);
                    *p = make_float2(v0, v1);
                }
                if (WSPLIT) {
                    bf16 h0, l0, h1, l1;
                    split2(v0, h0, l0); split2(v1, h1, l1);
                    *(__nv_bfloat162*)(Chi + (size_t)gr * ldcs + gc) =
                        __nv_bfloat162(h0, h1);
                    *(__nv_bfloat162*)(Clo + (size_t)gr * ldcs + gc) =
                        __nv_bfloat162(l0, l1);
                }
            }
        }
}

// ======================= prep kernels =======================
__global__ void prep_weight(const float* __restrict__ W, int K, int N, int Kpad, int total,
                            bf16* __restrict__ Whi, bf16* __restrict__ Wlo)
{
    int idx = blockIdx.x * blockDim.x + threadIdx.x;
    if (idx >= total) return;
    int n = idx / Kpad, k = idx - n * Kpad;
    float v = (k < K && n < N) ? W[(size_t)k * N + n] : 0.f;
    bf16 hi, lo; split2(v, hi, lo);
    Whi[idx] = hi; Wlo[idx] = lo;
}

__global__ void prep_act(const float* __restrict__ X, int total, int K, int Kpad,
                         bf16* __restrict__ Ahi, bf16* __restrict__ Alo)
{
    int idx = blockIdx.x * blockDim.x + threadIdx.x;
    if (idx >= total) return;
    int r = idx / Kpad, k = idx - r * Kpad;
    float v = (k < K) ? X[(size_t)r * K + k] : 0.f;
    bf16 hi, lo; split2(v, hi, lo);
    Ahi[idx] = hi; Alo[idx] = lo;
}

// ======================= LSTM gates (2 units/thread, fast math) ==========
__global__ void lstm_gates(const float* __restrict__ z, float* __restrict__ c,
                           bf16* __restrict__ hhi, bf16* __restrict__ hlo,
                           bf16* __restrict__ dhi, bf16* __restrict__ dlo, int t)
{
    int idx = blockIdx.x * blockDim.x + threadIdx.x;
    const int TOT = BSZ * (UU / 2);
    if (idx >= TOT) return;
    int b = idx / (UU / 2);
    int j = (idx - b * (UU / 2)) * 2;          // even unit index
    const float* zr = z + (size_t)b * GATES;
    float2 zi = *(const float2*)(zr + j);
    float2 zf = *(const float2*)(zr + UU + j);
    float2 zg = *(const float2*)(zr + 2 * UU + j);
    float2 zo = *(const float2*)(zr + 3 * UU + j);
    float2 cv = *(const float2*)(c + (size_t)b * UU + j);

    float cn0 = fsig(zf.x) * cv.x + fsig(zi.x) * ftanh(zg.x);
    float cn1 = fsig(zf.y) * cv.y + fsig(zi.y) * ftanh(zg.y);
    *(float2*)(c + (size_t)b * UU + j) = make_float2(cn0, cn1);
    float h0 = fsig(zo.x) * ftanh(cn0);
    float h1 = fsig(zo.y) * ftanh(cn1);

    bf16 a0, b0, a1, b1;
    split2(h0, a0, b0); split2(h1, a1, b1);
    *(__nv_bfloat162*)(hhi + (size_t)b * HPAD + j) = __nv_bfloat162(a0, a1);
    *(__nv_bfloat162*)(hlo + (size_t)b * HPAD + j) = __nv_bfloat162(b0, b1);
    if (dhi) {
        *(__nv_bfloat162*)(dhi + (size_t)b * DPAD + t * UU + j) = __nv_bfloat162(a0, a1);
        *(__nv_bfloat162*)(dlo + (size_t)b * DPAD + t * UU + j) = __nv_bfloat162(b0, b1);
    }
}

// ======================= host side =======================
template<int ACT, bool BIAS, bool CINIT, bool WF32, bool WSPLIT>
static inline void launch_mma(int M, int N, int Kpad,
                              const bf16* Ahi, const bf16* Alo,
                              const bf16* Bhi, const bf16* Blo,
                              const float* bias, const float* Ci, int ldci,
                              float* Cf, int ldc, bf16* Chi, bf16* Clo, int ldcs)
{
    dim3 grid((N + 127) / 128, M / 256);
    mma_gemm<ACT, BIAS, CINIT, WF32, WSPLIT><<<grid, 256, SMEM_BYTES>>>(
        M, N, Kpad, Ahi, Alo, Bhi, Blo, bias, Ci, ldci, Cf, ldc, Chi, Clo, ldcs);
}

static inline void set_attrs() {
    cudaFuncSetAttribute(mma_gemm<0, true,  false, true,  false>, cudaFuncAttributeMaxDynamicSharedMemorySize, SMEM_BYTES);
    cudaFuncSetAttribute(mma_gemm<0, false, true,  true,  false>, cudaFuncAttributeMaxDynamicSharedMemorySize, SMEM_BYTES);
    cudaFuncSetAttribute(mma_gemm<1, true,  false, false, true >, cudaFuncAttributeMaxDynamicSharedMemorySize, SMEM_BYTES);
    cudaFuncSetAttribute(mma_gemm<2, true,  false, false, true >, cudaFuncAttributeMaxDynamicSharedMemorySize, SMEM_BYTES);
}

extern "C" void kernel_launch(void* const* d_in, const int* /*in_sizes*/, int /*n_in*/,
                              void* d_out, int /*out_size*/)
{
    const float* x     = (const float*)d_in[0];
    const float* m     = (const float*)d_in[1];
    const float* enc_W = (const float*)d_in[2];
    const float* enc_U = (const float*)d_in[3];
    const float* enc_b = (const float*)d_in[4];
    const float* dec_W = (const float*)d_in[5];
    const float* dec_U = (const float*)d_in[6];
    const float* dec_b = (const float*)d_in[7];
    const float* W_map = (const float*)d_in[8];
    const float* b_map = (const float*)d_in[9];
    const float* W1    = (const float*)d_in[10];
    const float* b1    = (const float*)d_in[11];
    const float* W2    = (const float*)d_in[12];
    const float* b2    = (const float*)d_in[13];
    const float* W3    = (const float*)d_in[14];
    const float* b3    = (const float*)d_in[15];
    const float* W_out = (const float*)d_in[16];
    const float* b_out = (const float*)d_in[17];
    float* out = (float*)d_out;

    set_attrs();

    bf16 *xhi,*xlo,*mhi,*mlo,*hhi,*hlo,*dhi,*dlo,*t1hi,*t1lo,*t2hi,*t2lo;
    bf16 *eWh,*eWl,*dWh,*dWl,*eUh,*eUl,*dUh,*dUl,*wmh,*wml,*w1h,*w1l,*w2h,*w2l,*w3h,*w3l,*woh,*wol;
    float *xw,*z,*c;
    cudaGetSymbolAddress((void**)&xhi, g_xhi);  cudaGetSymbolAddress((void**)&xlo, g_xlo);
    cudaGetSymbolAddress((void**)&mhi, g_mhi);  cudaGetSymbolAddress((void**)&mlo, g_mlo);
    cudaGetSymbolAddress((void**)&hhi, g_hhi);  cudaGetSymbolAddress((void**)&hlo, g_hlo);
    cudaGetSymbolAddress((void**)&dhi, g_dhi);  cudaGetSymbolAddress((void**)&dlo, g_dlo);
    cudaGetSymbolAddress((void**)&t1hi, g_t1hi); cudaGetSymbolAddress((void**)&t1lo, g_t1lo);
    cudaGetSymbolAddress((void**)&t2hi, g_t2hi); cudaGetSymbolAddress((void**)&t2lo, g_t2lo);
    cudaGetSymbolAddress((void**)&eWh, w_encW_hi); cudaGetSymbolAddress((void**)&eWl, w_encW_lo);
    cudaGetSymbolAddress((void**)&dWh, w_decW_hi); cudaGetSymbolAddress((void**)&dWl, w_decW_lo);
    cudaGetSymbolAddress((void**)&eUh, w_encU_hi); cudaGetSymbolAddress((void**)&eUl, w_encU_lo);
    cudaGetSymbolAddress((void**)&dUh, w_decU_hi); cudaGetSymbolAddress((void**)&dUl, w_decU_lo);
    cudaGetSymbolAddress((void**)&wmh, w_map_hi);  cudaGetSymbolAddress((void**)&wml, w_map_lo);
    cudaGetSymbolAddress((void**)&w1h, w_1_hi);    cudaGetSymbolAddress((void**)&w1l, w_1_lo);
    cudaGetSymbolAddress((void**)&w2h, w_2_hi);    cudaGetSymbolAddress((void**)&w2l, w_2_lo);
    cudaGetSymbolAddress((void**)&w3h, w_3_hi);    cudaGetSymbolAddress((void**)&w3l, w_3_lo);
    cudaGetSymbolAddress((void**)&woh, w_out_hi);  cudaGetSymbolAddress((void**)&wol, w_out_lo);
    cudaGetSymbolAddress((void**)&xw, g_xw);
    cudaGetSymbolAddress((void**)&z,  g_z);
    cudaGetSymbolAddress((void**)&c,  g_c);

    // init states + padding tails
    cudaMemsetAsync(c,   0, (size_t)BSZ * UU * sizeof(float));
    cudaMemsetAsync(hhi, 0, (size_t)BSZ * HPAD * sizeof(bf16));
    cudaMemsetAsync(hlo, 0, (size_t)BSZ * HPAD * sizeof(bf16));
    cudaMemsetAsync(dhi, 0, (size_t)BSZ * DPAD * sizeof(bf16));
    cudaMemsetAsync(dlo, 0, (size_t)BSZ * DPAD * sizeof(bf16));

    // weight prep (transpose + hi/lo split, padded)
    auto pw = [](const float* W, int K, int N, int Kpad, int Npad, bf16* hi, bf16* lo) {
        int total = Npad * Kpad;
        prep_weight<<<(total + 255) / 256, 256>>>(W, K, N, Kpad, total, hi, lo);
    };
    pw(enc_W, FENC, GATES, XPAD, GNPAD, eWh, eWl);
    pw(dec_W, FDEC, GATES, MPAD, GNPAD, dWh, dWl);
    pw(enc_U, UU,   GATES, HPAD, GNPAD, eUh, eUl);
    pw(dec_U, UU,   GATES, HPAD, GNPAD, dUh, dUl);
    pw(W_map, TS*UU, H1, DPAD, H1, wmh, wml);
    pw(W1, H1, H1, H1, H1, w1h, w1l);
    pw(W2, H1, H1, H1, H1, w2h, w2l);
    pw(W3, H1, H1, H1, H1, w3h, w3l);
    pw(W_out, H1, OUTN, H1, ONPAD, woh, wol);

    // activation prep
    {
        int tot = BT * XPAD;
        prep_act<<<(tot + 255) / 256, 256>>>(x, tot, FENC, XPAD, xhi, xlo);
        tot = BT * MPAD;
        prep_act<<<(tot + 255) / 256, 256>>>(m, tot, FDEC, MPAD, mhi, mlo);
    }

    const int gate_grid = (BSZ * (UU / 2) + 255) / 256;

    // encoder input projection: xw = x @ enc_W + enc_b
    launch_mma<0, true, false, true, false>(BT, GATES, XPAD, xhi, xlo, eWh, eWl,
                                            enc_b, nullptr, 0, xw, GATES, nullptr, nullptr, 0);
    for (int t = 0; t < TS; t++) {
        launch_mma<0, false, true, true, false>(BSZ, GATES, HPAD, hhi, hlo, eUh, eUl,
                                                nullptr, xw + (size_t)t * GATES, TS * GATES,
                                                z, GATES, nullptr, nullptr, 0);
        lstm_gates<<<gate_grid, 256>>>(z, c, hhi, hlo, nullptr, nullptr, 0);
    }

    // decoder input projection (reuse xw)
    launch_mma<0, true, false, true, false>(BT, GATES, MPAD, mhi, mlo, dWh, dWl,
                                            dec_b, nullptr, 0, xw, GATES, nullptr, nullptr, 0);
    for (int t = 0; t < TS; t++) {
        launch_mma<0, false, true, true, false>(BSZ, GATES, HPAD, hhi, hlo, dUh, dUl,
                                                nullptr, xw + (size_t)t * GATES, TS * GATES,
                                                z, GATES, nullptr, nullptr, 0);
        lstm_gates<<<gate_grid, 256>>>(z, c, hhi, hlo, dhi, dlo, t);
    }

    // MLP head
    launch_mma<1, true, false, false, true>(BSZ, H1, DPAD, dhi, dlo, wmh, wml,
                                            b_map, nullptr, 0, nullptr, 0, t1hi, t1lo, H1);
    launch_mma<2, true, false, false, true>(BSZ, H1, H1, t1hi, t1lo, w1h, w1l,
                                            b1, nullptr, 0, nullptr, 0, t2hi, t2lo, H1);
    launch_mma<2, true, false, false, true>(BSZ, H1, H1, t2hi, t2lo, w2h, w2l,
                                            b2, nullptr, 0, nullptr, 0, t1hi, t1lo, H1);
    launch_mma<2, true, false, false, true>(BSZ, H1, H1, t1hi, t1lo, w3h, w3l,
                                            b3, nullptr, 0, nullptr, 0, t2hi, t2lo, H1);
    launch_mma<0, true, false, true, false>(BSZ, OUTN, H1, t2hi, t2lo, woh, wol,
                                            b_out, nullptr, 0, out, OUTN, nullptr, nullptr, 0);
}

// round 8
// speedup vs baseline: 1.9608x; 1.3420x over previous
#include <cuda_runtime.h>
#include <cuda_fp16.h>
#include <cstdint>
#include <math.h>

// ======================= problem dims =======================
#define UU      356
#define GATES   1424
#define BSZ     8192
#define TS      7
#define FENC    69
#define FDEC    45
#define H1      1024
#define OUTN    168

#define HPAD    384
#define XPAD    128
#define MPAD    64
#define DPAD    2496
#define GNPAD   1536
#define ONPAD   256
#define BT      (BSZ*TS)

// ======================= scratch (device globals) =======================
// activations: single fp16
__device__ __half g_x[(size_t)BT*XPAD];
__device__ __half g_m[(size_t)BT*MPAD];
__device__ float  g_xw[(size_t)BT*GATES];
__device__ float  g_z [(size_t)BSZ*GATES];
__device__ float  g_c [(size_t)BSZ*UU];
__device__ __half g_h [(size_t)BSZ*HPAD];
__device__ __half g_d [(size_t)BSZ*DPAD];
__device__ __half g_t1[(size_t)BSZ*H1];
__device__ __half g_t2[(size_t)BSZ*H1];
// weights: transposed, padded [Npad, Kpad], split fp16 hi/lo
__device__ __half w_encW_hi[(size_t)GNPAD*XPAD], w_encW_lo[(size_t)GNPAD*XPAD];
__device__ __half w_decW_hi[(size_t)GNPAD*MPAD], w_decW_lo[(size_t)GNPAD*MPAD];
__device__ __half w_encU_hi[(size_t)GNPAD*HPAD], w_encU_lo[(size_t)GNPAD*HPAD];
__device__ __half w_decU_hi[(size_t)GNPAD*HPAD], w_decU_lo[(size_t)GNPAD*HPAD];
__device__ __half w_map_hi[(size_t)H1*DPAD],     w_map_lo[(size_t)H1*DPAD];
__device__ __half w_1_hi[(size_t)H1*H1], w_1_lo[(size_t)H1*H1];
__device__ __half w_2_hi[(size_t)H1*H1], w_2_lo[(size_t)H1*H1];
__device__ __half w_3_hi[(size_t)H1*H1], w_3_lo[(size_t)H1*H1];
__device__ __half w_out_hi[(size_t)ONPAD*H1],    w_out_lo[(size_t)ONPAD*H1];

// ======================= PTX helpers (sm_80-era) =======================
__device__ __forceinline__ uint32_t smem_u32(const void* p) {
    uint32_t a;
    asm("{ .reg .u64 t; cvta.to.shared.u64 t, %1; cvt.u32.u64 %0, t; }" : "=r"(a) : "l"(p));
    return a;
}
#define CP_ASYNC16(dst, src) \
    asm volatile("cp.async.cg.shared.global [%0], [%1], 16;" :: "r"(dst), "l"(src))
#define CP_COMMIT()  asm volatile("cp.async.commit_group;" ::: "memory")
#define CP_WAIT1()   asm volatile("cp.async.wait_group 1;" ::: "memory")
#define LDSM4(r0,r1,r2,r3,addr) \
    asm volatile("ldmatrix.sync.aligned.m8n8.x4.shared.b16 {%0,%1,%2,%3}, [%4];" \
        : "=r"(r0),"=r"(r1),"=r"(r2),"=r"(r3) : "r"(addr))

__device__ __forceinline__ void mma16816(float* d, const uint32_t* a, const uint32_t* b) {
    asm volatile("mma.sync.aligned.m16n8k16.row.col.f32.f16.f16.f32 "
        "{%0,%1,%2,%3}, {%4,%5,%6,%7}, {%8,%9}, {%0,%1,%2,%3};"
        : "+f"(d[0]), "+f"(d[1]), "+f"(d[2]), "+f"(d[3])
        : "r"(a[0]), "r"(a[1]), "r"(a[2]), "r"(a[3]), "r"(b[0]), "r"(b[1]));
}

// fast transcendentals (MUFU-based)
__device__ __forceinline__ float fsig(float x) {
    return __fdividef(1.f, 1.f + __expf(-x));
}
__device__ __forceinline__ float ftanh(float x) {
    return __fmaf_rn(2.f, fsig(2.f * x), -1.f);
}

// ======================= HMMA GEMM =======================
// C[M,N] = act( A @ B^T (+Ci) (+bias) )
// A:[M,Kpad] single fp16; B:[Npad,Kpad] fp16 hi/lo split.
// CTA 256x128, BK=32, 8 warps (4 M x 2 N), warp tile 64x64, 3-stage cp.async.
#define ROWB    80
#define A_TILEB (256*ROWB)                 // 20480
#define B_TILEB (128*ROWB)                 // 10240
#define STAGE   (A_TILEB + 2*B_TILEB)      // 40960
#define NSTAGE  3
#define SMEM_BYTES (NSTAGE*STAGE)          // 122880

template<int ACT, bool BIAS, bool CINIT, bool WF32, bool WH>
__global__ __launch_bounds__(256)
void mma_gemm(int M, int N, int Kpad,
              const __half* __restrict__ A,
              const __half* __restrict__ Bhi, const __half* __restrict__ Blo,
              const float* __restrict__ bias,
              const float* __restrict__ Ci, int ldci,
              float* __restrict__ Cf, int ldc,
              __half* __restrict__ Ch, int ldcs)
{
    extern __shared__ char smem[];
    const uint32_t sbase = smem_u32(smem);
    const int tid  = threadIdx.x;
    const int lane = tid & 31;
    const int wid  = tid >> 5;
    const int warp_m = wid & 3;
    const int warp_n = wid >> 2;
    const int bm = blockIdx.y * 256;
    const int bn = blockIdx.x * 128;

    const int ld = Kpad * 2;
    const char* gA   = (const char*)A   + (size_t)bm * ld;
    const char* gBhi = (const char*)Bhi + (size_t)bn * ld;
    const char* gBlo = (const char*)Blo + (size_t)bn * ld;

    const int rr  = tid >> 2;
    const int seg = (tid & 3) * 16;

    float acc[4][8][4];
    #pragma unroll
    for (int i = 0; i < 4; i++)
        #pragma unroll
        for (int j = 0; j < 8; j++)
            #pragma unroll
            for (int q = 0; q < 4; q++) acc[i][j][q] = 0.f;

    const int NC = Kpad >> 5;

    auto stage_load = [&](int c) {
        uint32_t s = sbase + (c % NSTAGE) * STAGE;
        int ko = c << 6;
        #pragma unroll
        for (int i = 0; i < 4; i++) {
            int r = rr + i * 64;
            CP_ASYNC16(s + r*ROWB + seg, gA + (size_t)r*ld + ko + seg);
        }
        #pragma unroll
        for (int i = 0; i < 2; i++) {
            int r = rr + i * 64;
            CP_ASYNC16(s + A_TILEB + 0*B_TILEB + r*ROWB + seg, gBhi + (size_t)r*ld + ko + seg);
            CP_ASYNC16(s + A_TILEB + 1*B_TILEB + r*ROWB + seg, gBlo + (size_t)r*ld + ko + seg);
        }
    };

    stage_load(0); CP_COMMIT();
    if (NC > 1) { stage_load(1); }
    CP_COMMIT();

    const uint32_t aoff = (uint32_t)((warp_m*64 + (lane & 15)) * ROWB + (lane >> 4) * 16);
    const uint32_t boff = (uint32_t)((warp_n*64 + (lane >> 4)*8 + (lane & 7)) * ROWB
                                     + ((lane >> 3) & 1) * 16);

    for (int c = 0; c < NC; c++) {
        CP_WAIT1();
        __syncthreads();
        if (c + 2 < NC) stage_load(c + 2);
        CP_COMMIT();

        const uint32_t sb  = sbase + (c % NSTAGE) * STAGE;
        const uint32_t sA  = sb;
        const uint32_t sB0 = sb + A_TILEB;
        const uint32_t sB1 = sB0 + B_TILEB;

        #pragma unroll
        for (int kk = 0; kk < 2; kk++) {
            const uint32_t kb = kk * 32;
            uint32_t a[4][4], bhi[4][4], blo[4][4];
            #pragma unroll
            for (int mi = 0; mi < 4; mi++) {
                uint32_t ad = sA + aoff + mi * (16 * ROWB) + kb;
                LDSM4(a[mi][0], a[mi][1], a[mi][2], a[mi][3], ad);
            }
            #pragma unroll
            for (int g = 0; g < 4; g++) {
                uint32_t b = boff + g * (16 * ROWB) + kb;
                LDSM4(bhi[g][0], bhi[g][1], bhi[g][2], bhi[g][3], sB0 + b);
                LDSM4(blo[g][0], blo[g][1], blo[g][2], blo[g][3], sB1 + b);
            }
            #pragma unroll
            for (int mi = 0; mi < 4; mi++)
                #pragma unroll
                for (int nj = 0; nj < 8; nj++) {
                    const uint32_t* bh = &bhi[nj >> 1][(nj & 1) * 2];
                    const uint32_t* bl = &blo[nj >> 1][(nj & 1) * 2];
                    mma16816(acc[mi][nj], a[mi], bh);
                    mma16816(acc[mi][nj], a[mi], bl);
                }
        }
        __syncthreads();
    }

    // ---- epilogue: registers -> global ----
    const int tr = lane >> 2;
    const int tc = (lane & 3) * 2;
    const int row0 = bm + warp_m * 64;
    const int col0 = bn + warp_n * 64;
    #pragma unroll
    for (int mi = 0; mi < 4; mi++)
        #pragma unroll
        for (int nj = 0; nj < 8; nj++) {
            int gc = col0 + nj * 8 + tc;
            if (gc >= N) continue;
            float b0 = 0.f, b1 = 0.f;
            if (BIAS) { b0 = bias[gc]; b1 = bias[gc + 1]; }
            #pragma unroll
            for (int hh = 0; hh < 2; hh++) {
                int gr = row0 + mi * 16 + hh * 8 + tr;
                float v0 = acc[mi][nj][hh * 2 + 0];
                float v1 = acc[mi][nj][hh * 2 + 1];
                if (CINIT) {
                    const float* ci = Ci + (size_t)gr * ldci + gc;
                    v0 += ci[0]; v1 += ci[1];
                }
                if (BIAS) { v0 += b0; v1 += b1; }
                if (ACT == 1) { v0 = fmaxf(v0, 0.f); v1 = fmaxf(v1, 0.f); }
                else if (ACT == 2) { v0 = ftanh(v0); v1 = ftanh(v1); }
                if (WF32) {
                    float2* p = (float2*)(Cf + (size_t)gr * ldc + gc);
                    *p = make_float2(v0, v1);
                }
                if (WH) {
                    *(__half2*)(Ch + (size_t)gr * ldcs + gc) =
                        __floats2half2_rn(v0, v1);
                }
            }
        }
}

// ======================= prep kernels =======================
__global__ void prep_weight(const float* __restrict__ W, int K, int N, int Kpad, int total,
                            __half* __restrict__ Whi, __half* __restrict__ Wlo)
{
    int idx = blockIdx.x * blockDim.x + threadIdx.x;
    if (idx >= total) return;
    int n = idx / Kpad, k = idx - n * Kpad;
    float v = (k < K && n < N) ? W[(size_t)k * N + n] : 0.f;
    __half hi = __float2half_rn(v);
    Whi[idx] = hi;
    Wlo[idx] = __float2half_rn(v - __half2float(hi));
}

__global__ void prep_act(const float* __restrict__ X, int total, int K, int Kpad,
                         __half* __restrict__ A)
{
    int idx = blockIdx.x * blockDim.x + threadIdx.x;
    if (idx >= total) return;
    int r = idx / Kpad, k = idx - r * Kpad;
    A[idx] = __float2half_rn((k < K) ? X[(size_t)r * K + k] : 0.f);
}

// ======================= LSTM gates (2 units/thread, fast math) ==========
__global__ void lstm_gates(const float* __restrict__ z, float* __restrict__ c,
                           __half* __restrict__ h, __half* __restrict__ d, int t)
{
    int idx = blockIdx.x * blockDim.x + threadIdx.x;
    const int TOT = BSZ * (UU / 2);
    if (idx >= TOT) return;
    int b = idx / (UU / 2);
    int j = (idx - b * (UU / 2)) * 2;
    const float* zr = z + (size_t)b * GATES;
    float2 zi = *(const float2*)(zr + j);
    float2 zf = *(const float2*)(zr + UU + j);
    float2 zg = *(const float2*)(zr + 2 * UU + j);
    float2 zo = *(const float2*)(zr + 3 * UU + j);
    float2 cv = *(const float2*)(c + (size_t)b * UU + j);

    float cn0 = fsig(zf.x) * cv.x + fsig(zi.x) * ftanh(zg.x);
    float cn1 = fsig(zf.y) * cv.y + fsig(zi.y) * ftanh(zg.y);
    *(float2*)(c + (size_t)b * UU + j) = make_float2(cn0, cn1);
    __half2 hv = __floats2half2_rn(fsig(zo.x) * ftanh(cn0),
                                   fsig(zo.y) * ftanh(cn1));
    *(__half2*)(h + (size_t)b * HPAD + j) = hv;
    if (d) *(__half2*)(d + (size_t)b * DPAD + t * UU + j) = hv;
}

// ======================= host side =======================
template<int ACT, bool BIAS, bool CINIT, bool WF32, bool WH>
static inline void launch_mma(int M, int N, int Kpad,
                              const __half* A, const __half* Bhi, const __half* Blo,
                              const float* bias, const float* Ci, int ldci,
                              float* Cf, int ldc, __half* Ch, int ldcs)
{
    dim3 grid((N + 127) / 128, M / 256);
    mma_gemm<ACT, BIAS, CINIT, WF32, WH><<<grid, 256, SMEM_BYTES>>>(
        M, N, Kpad, A, Bhi, Blo, bias, Ci, ldci, Cf, ldc, Ch, ldcs);
}

static inline void set_attrs() {
    cudaFuncSetAttribute(mma_gemm<0, true,  false, true,  false>, cudaFuncAttributeMaxDynamicSharedMemorySize, SMEM_BYTES);
    cudaFuncSetAttribute(mma_gemm<0, false, true,  true,  false>, cudaFuncAttributeMaxDynamicSharedMemorySize, SMEM_BYTES);
    cudaFuncSetAttribute(mma_gemm<1, true,  false, false, true >, cudaFuncAttributeMaxDynamicSharedMemorySize, SMEM_BYTES);
    cudaFuncSetAttribute(mma_gemm<2, true,  false, false, true >, cudaFuncAttributeMaxDynamicSharedMemorySize, SMEM_BYTES);
}

extern "C" void kernel_launch(void* const* d_in, const int* /*in_sizes*/, int /*n_in*/,
                              void* d_out, int /*out_size*/)
{
    const float* x     = (const float*)d_in[0];
    const float* m     = (const float*)d_in[1];
    const float* enc_W = (const float*)d_in[2];
    const float* enc_U = (const float*)d_in[3];
    const float* enc_b = (const float*)d_in[4];
    const float* dec_W = (const float*)d_in[5];
    const float* dec_U = (const float*)d_in[6];
    const float* dec_b = (const float*)d_in[7];
    const float* W_map = (const float*)d_in[8];
    const float* b_map = (const float*)d_in[9];
    const float* W1    = (const float*)d_in[10];
    const float* b1    = (const float*)d_in[11];
    const float* W2    = (const float*)d_in[12];
    const float* b2    = (const float*)d_in[13];
    const float* W3    = (const float*)d_in[14];
    const float* b3    = (const float*)d_in[15];
    const float* W_out = (const float*)d_in[16];
    const float* b_out = (const float*)d_in[17];
    float* out = (float*)d_out;

    set_attrs();

    __half *xa,*ma,*h,*d,*t1,*t2;
    __half *eWh,*eWl,*dWh,*dWl,*eUh,*eUl,*dUh,*dUl,*wmh,*wml,*w1h,*w1l,*w2h,*w2l,*w3h,*w3l,*woh,*wol;
    float *xw,*z,*c;
    cudaGetSymbolAddress((void**)&xa, g_x);   cudaGetSymbolAddress((void**)&ma, g_m);
    cudaGetSymbolAddress((void**)&h,  g_h);   cudaGetSymbolAddress((void**)&d,  g_d);
    cudaGetSymbolAddress((void**)&t1, g_t1);  cudaGetSymbolAddress((void**)&t2, g_t2);
    cudaGetSymbolAddress((void**)&eWh, w_encW_hi); cudaGetSymbolAddress((void**)&eWl, w_encW_lo);
    cudaGetSymbolAddress((void**)&dWh, w_decW_hi); cudaGetSymbolAddress((void**)&dWl, w_decW_lo);
    cudaGetSymbolAddress((void**)&eUh, w_encU_hi); cudaGetSymbolAddress((void**)&eUl, w_encU_lo);
    cudaGetSymbolAddress((void**)&dUh, w_decU_hi); cudaGetSymbolAddress((void**)&dUl, w_decU_lo);
    cudaGetSymbolAddress((void**)&wmh, w_map_hi);  cudaGetSymbolAddress((void**)&wml, w_map_lo);
    cudaGetSymbolAddress((void**)&w1h, w_1_hi);    cudaGetSymbolAddress((void**)&w1l, w_1_lo);
    cudaGetSymbolAddress((void**)&w2h, w_2_hi);    cudaGetSymbolAddress((void**)&w2l, w_2_lo);
    cudaGetSymbolAddress((void**)&w3h, w_3_hi);    cudaGetSymbolAddress((void**)&w3l, w_3_lo);
    cudaGetSymbolAddress((void**)&woh, w_out_hi);  cudaGetSymbolAddress((void**)&wol, w_out_lo);
    cudaGetSymbolAddress((void**)&xw, g_xw);
    cudaGetSymbolAddress((void**)&z,  g_z);
    cudaGetSymbolAddress((void**)&c,  g_c);

    // init states + padding tails
    cudaMemsetAsync(c, 0, (size_t)BSZ * UU * sizeof(float));
    cudaMemsetAsync(h, 0, (size_t)BSZ * HPAD * sizeof(__half));
    cudaMemsetAsync(d, 0, (size_t)BSZ * DPAD * sizeof(__half));

    // weight prep (transpose + hi/lo split, padded)
    auto pw = [](const float* W, int K, int N, int Kpad, int Npad, __half* hi, __half* lo) {
        int total = Npad * Kpad;
        prep_weight<<<(total + 255) / 256, 256>>>(W, K, N, Kpad, total, hi, lo);
    };
    pw(enc_W, FENC, GATES, XPAD, GNPAD, eWh, eWl);
    pw(dec_W, FDEC, GATES, MPAD, GNPAD, dWh, dWl);
    pw(enc_U, UU,   GATES, HPAD, GNPAD, eUh, eUl);
    pw(dec_U, UU,   GATES, HPAD, GNPAD, dUh, dUl);
    pw(W_map, TS*UU, H1, DPAD, H1, wmh, wml);
    pw(W1, H1, H1, H1, H1, w1h, w1l);
    pw(W2, H1, H1, H1, H1, w2h, w2l);
    pw(W3, H1, H1, H1, H1, w3h, w3l);
    pw(W_out, H1, OUTN, H1, ONPAD, woh, wol);

    // activation prep
    {
        int tot = BT * XPAD;
        prep_act<<<(tot + 255) / 256, 256>>>(x, tot, FENC, XPAD, xa);
        tot = BT * MPAD;
        prep_act<<<(tot + 255) / 256, 256>>>(m, tot, FDEC, MPAD, ma);
    }

    const int gate_grid = (BSZ * (UU / 2) + 255) / 256;

    // encoder input projection: xw = x @ enc_W + enc_b
    launch_mma<0, true, false, true, false>(BT, GATES, XPAD, xa, eWh, eWl,
                                            enc_b, nullptr, 0, xw, GATES, nullptr, 0);
    for (int t = 0; t < TS; t++) {
        launch_mma<0, false, true, true, false>(BSZ, GATES, HPAD, h, eUh, eUl,
                                                nullptr, xw + (size_t)t * GATES, TS * GATES,
                                                z, GATES, nullptr, 0);
        lstm_gates<<<gate_grid, 256>>>(z, c, h, nullptr, 0);
    }

    // decoder input projection (reuse xw)
    launch_mma<0, true, false, true, false>(BT, GATES, MPAD, ma, dWh, dWl,
                                            dec_b, nullptr, 0, xw, GATES, nullptr, 0);
    for (int t = 0; t < TS; t++) {
        launch_mma<0, false, true, true, false>(BSZ, GATES, HPAD, h, dUh, dUl,
                                                nullptr, xw + (size_t)t * GATES, TS * GATES,
                                                z, GATES, nullptr, 0);
        lstm_gates<<<gate_grid, 256>>>(z, c, h, d, t);
    }

    // MLP head
    launch_mma<1, true, false, false, true>(BSZ, H1, DPAD, d, wmh, wml,
                                            b_map, nullptr, 0, nullptr, 0, t1, H1);
    launch_mma<2, true, false, false, true>(BSZ, H1, H1, t1, w1h, w1l,
                                            b1, nullptr, 0, nullptr, 0, t2, H1);
    launch_mma<2, true, false, false, true>(BSZ, H1, H1, t2, w2h, w2l,
                                            b2, nullptr, 0, nullptr, 0, t1, H1);
    launch_mma<2, true, false, false, true>(BSZ, H1, H1, t1, w3h, w3l,
                                            b3, nullptr, 0, nullptr, 0, t2, H1);
    launch_mma<0, true, false, true, false>(BSZ, OUTN, H1, t2, woh, wol,
                                            b_out, nullptr, 0, out, OUTN, nullptr, 0);
}